// round 5
// baseline (speedup 1.0000x reference)
#include <cuda_runtime.h>
#include <cuda_bf16.h>
#include <cstdint>

#define D_DIM   256
#define NPATCH  16384
#define VOCAB   4096

#define NVT     16          // vocab tiles of 256 rows
#define VTN     256         // vocab rows per tile
#define CHM     64          // patches per chunk
#define NGRP    9           // patch groups (grid = 144)
#define NCHUNK  (NPATCH / CHM)   // 256 chunks total

#define B_BYTES (VTN * 512)              // 131072 (vocab tile, full K, bf16)
#define A_STAGE (CHM * 512)              // 32768
#define SMEM_BYTES (B_BYTES + 2 * A_STAGE)  // 196608

__device__ float         g_v2[VOCAB];
__device__ __nv_bfloat16 g_pb[NPATCH * D_DIM];
__device__ __nv_bfloat16 g_vb[VOCAB * D_DIM];
__device__ uint2         g_cand[64 * NPATCH];   // [vt*4+wn][patch] best-2 keys

#define CP_ASYNC16(dst, src) \
    asm volatile("cp.async.cg.shared.global [%0], [%1], 16;" :: "r"((uint32_t)(dst)), "l"(src))
#define CP_COMMIT() asm volatile("cp.async.commit_group;" ::: "memory")

__device__ __forceinline__ void mma16(float* c, uint32_t a0, uint32_t a1, uint32_t a2, uint32_t a3,
                                      uint32_t b0, uint32_t b1) {
    asm("mma.sync.aligned.m16n8k16.row.col.f32.bf16.bf16.f32 "
        "{%0,%1,%2,%3}, {%4,%5,%6,%7}, {%8,%9}, {%0,%1,%2,%3};"
        : "+f"(c[0]), "+f"(c[1]), "+f"(c[2]), "+f"(c[3])
        : "r"(a0), "r"(a1), "r"(a2), "r"(a3), "r"(b0), "r"(b1));
}

// order-preserving float->uint key, vocab idx in low 12 bits
__device__ __forceinline__ uint32_t fkey(float s, int n) {
    uint32_t b = __float_as_uint(s);
    uint32_t u = b ^ (uint32_t)(((int32_t)b >> 31) | 0x80000000);
    return (u & 0xFFFFF000u) | (uint32_t)n;
}
__device__ __forceinline__ float unkey(uint32_t key) {
    uint32_t u = key & 0xFFFFF000u;
    uint32_t b = (u & 0x80000000u) ? (u ^ 0x80000000u) : ~u;
    return __uint_as_float(b);
}

// within a 32-k block: lane t's 16B covers both k16 groups (proven in R4)
__device__ __forceinline__ int perm32(int k) {
    return ((k & 7) >> 1) * 8 + ((k >> 4) & 1) * 4 + ((k >> 3) & 1) * 2 + (k & 1);
}

// ---------------------------------------------------------------------------
// prep kernels
// ---------------------------------------------------------------------------
__global__ void v2_kernel(const float* __restrict__ vocab, int V) {
    int v = blockIdx.x * 8 + (threadIdx.x >> 5);
    int lane = threadIdx.x & 31;
    if (v >= V) return;
    const float* row = vocab + v * D_DIM;
    float s = 0.f;
#pragma unroll
    for (int k = lane; k < D_DIM; k += 32) { float x = row[k]; s += x * x; }
#pragma unroll
    for (int o = 16; o > 0; o >>= 1) s += __shfl_down_sync(0xffffffffu, s, o);
    if (lane == 0) g_v2[v] = s;
}

__global__ void patchify_bf_kernel(const float* __restrict__ images,
                                   float* __restrict__ patches, int total) {
    int idx = blockIdx.x * blockDim.x + threadIdx.x;
    if (idx >= total) return;
    int d = idx & 255, n = (idx >> 8) & 255, b = idx >> 16;
    int ph = n >> 4, pw = n & 15, i = d >> 4, j = d & 15;
    float x = images[(b << 16) + ((ph * 16 + i) << 8) + pw * 16 + j];
    patches[idx] = x;
    g_pb[(idx & ~255) + (d & ~31) + perm32(d & 31)] = __float2bfloat16_rn(x);
}

__global__ void vocab_bf_kernel(const float* __restrict__ vocab, int total) {
    int idx = blockIdx.x * blockDim.x + threadIdx.x;
    if (idx >= total) return;
    int d = idx & 255;
    g_vb[(idx & ~255) + (d & ~31) + perm32(d & 31)] = __float2bfloat16_rn(vocab[idx]);
}

// ---------------------------------------------------------------------------
// vq: vocab tile resident (full K), stream patch chunks, best2 per 64-col group
// ---------------------------------------------------------------------------
__global__ __launch_bounds__(256, 1)
void vq_kernel() {
    extern __shared__ char sm[];
    const uint32_t smem = (uint32_t)__cvta_generic_to_shared(sm);
    const uint32_t smB = smem;
    const uint32_t smA = smem + B_BYTES;

    const int tid  = threadIdx.x;
    const int lane = tid & 31;
    const int wid  = tid >> 5;
    const int g    = lane >> 2;
    const int t    = lane & 3;
    const int wm   = wid & 1;           // 2 m-warps (32 patch rows)
    const int wn   = wid >> 1;          // 4 n-warps (64 vocab cols)

    const int vt  = blockIdx.x & 15;
    const int grp = blockIdx.x >> 4;
    const int c0  = (grp * NCHUNK) / NGRP;
    const int c1  = ((grp + 1) * NCHUNK) / NGRP;

    // ---- prologue: resident B tile + A chunk c0, one commit group ----
    {
        const __nv_bfloat16* srcB = g_vb + (size_t)(vt * VTN + tid) * D_DIM;
        const uint32_t dB = smB + tid * 512;
        const uint32_t sw = (uint32_t)(tid & 7) << 2;
#pragma unroll
        for (int u = 0; u < 32; u++)
            CP_ASYNC16(dB + (((uint32_t)u ^ sw) << 4), srcB + u * 8);
        const int r = tid >> 2, q = tid & 3;
        const __nv_bfloat16* srcA = g_pb + (size_t)(c0 * CHM + r) * D_DIM;
        const uint32_t swA = (uint32_t)(r & 7) << 2;
#pragma unroll
        for (int uu = 0; uu < 8; uu++) {
            const int u = q * 8 + uu;
            CP_ASYNC16(smA + r * 512 + (((uint32_t)u ^ swA) << 4), srcA + u * 8);
        }
        CP_COMMIT();
    }

    // v2 for owned columns (16 per thread), in registers
    float v2r[16];
#pragma unroll
    for (int j = 0; j < 8; j++)
#pragma unroll
        for (int e = 0; e < 2; e++)
            v2r[j * 2 + e] = __ldg(g_v2 + vt * VTN + wn * 64 + j * 8 + 2 * t + e);

#define BEST2(sl, kv) do { \
        uint32_t _k = (kv); \
        uint32_t _x1 = max(kb1[sl], _k); \
        kb1[sl] = min(kb1[sl], _k); \
        kb2[sl] = min(kb2[sl], _x1); \
    } while (0)

#pragma unroll 1
    for (int c = c0; c < c1; c++) {
        const int lc = c - c0;
        // prefetch next A chunk into the other stage
        if (c + 1 < c1) {
            const int r = tid >> 2, q = tid & 3;
            const __nv_bfloat16* srcA = g_pb + (size_t)((c + 1) * CHM + r) * D_DIM;
            const uint32_t dA = smA + ((lc + 1) & 1) * A_STAGE + r * 512;
            const uint32_t swA = (uint32_t)(r & 7) << 2;
#pragma unroll
            for (int uu = 0; uu < 8; uu++) {
                const int u = q * 8 + uu;
                CP_ASYNC16(dA + (((uint32_t)u ^ swA) << 4), srcA + u * 8);
            }
            CP_COMMIT();
            asm volatile("cp.async.wait_group 1;" ::: "memory");
        } else {
            asm volatile("cp.async.wait_group 0;" ::: "memory");
        }
        __syncthreads();

        const char* Ab = sm + B_BYTES + (lc & 1) * A_STAGE;
        float acc[2][8][4];
#pragma unroll
        for (int i = 0; i < 2; i++)
#pragma unroll
            for (int j = 0; j < 8; j++)
#pragma unroll
                for (int e = 0; e < 4; e++) acc[i][j][e] = 0.f;

#pragma unroll
        for (int kb = 0; kb < 8; kb++) {
            const uint32_t aoff = (uint32_t)((((kb ^ g) << 2) | t) << 4);
            uint4 af[2][2];
#pragma unroll
            for (int i = 0; i < 2; i++)
#pragma unroll
                for (int h = 0; h < 2; h++)
                    af[i][h] = *(const uint4*)(Ab + (wm * 32 + i * 16 + h * 8 + g) * 512 + aoff);
#pragma unroll
            for (int j = 0; j < 8; j++) {
                const int n = wn * 64 + j * 8 + g;      // n & 7 == g
                const uint4 bf = *(const uint4*)(sm + n * 512 + aoff);
#pragma unroll
                for (int i = 0; i < 2; i++) {
                    float* cacc = acc[i][j];
                    mma16(cacc, af[i][0].x, af[i][1].x, af[i][0].y, af[i][1].y, bf.x, bf.y);
                    mma16(cacc, af[i][0].z, af[i][1].z, af[i][0].w, af[i][1].w, bf.z, bf.w);
                }
            }
        }

        // epilogue: per-row best2 over this warp's 64 cols
        uint32_t kb1[4], kb2[4];
#pragma unroll
        for (int sl = 0; sl < 4; sl++) { kb1[sl] = 0xFFFFFFFFu; kb2[sl] = 0xFFFFFFFFu; }
#pragma unroll
        for (int j = 0; j < 8; j++) {
            const int nn = vt * VTN + wn * 64 + j * 8 + 2 * t;
#pragma unroll
            for (int i = 0; i < 2; i++) {
                BEST2(i * 2 + 0, fkey(v2r[j * 2 + 0] - 2.f * acc[i][j][0], nn));
                BEST2(i * 2 + 0, fkey(v2r[j * 2 + 1] - 2.f * acc[i][j][1], nn + 1));
                BEST2(i * 2 + 1, fkey(v2r[j * 2 + 0] - 2.f * acc[i][j][2], nn));
                BEST2(i * 2 + 1, fkey(v2r[j * 2 + 1] - 2.f * acc[i][j][3], nn + 1));
            }
        }
        // combine across the 4 t-lanes sharing each row
#pragma unroll
        for (int o = 1; o <= 2; o <<= 1) {
#pragma unroll
            for (int sl = 0; sl < 4; sl++) {
                const uint32_t o1 = __shfl_xor_sync(0xffffffffu, kb1[sl], o);
                const uint32_t o2 = __shfl_xor_sync(0xffffffffu, kb2[sl], o);
                const uint32_t x1 = max(kb1[sl], o1);
                kb1[sl] = min(kb1[sl], o1);
                kb2[sl] = min(min(kb2[sl], o2), x1);
            }
        }
        if (t == 0) {
#pragma unroll
            for (int i = 0; i < 2; i++)
#pragma unroll
                for (int h = 0; h < 2; h++) {
                    const int row = c * CHM + wm * 32 + i * 16 + h * 8 + g;
                    g_cand[(vt * 4 + wn) * NPATCH + row] =
                        make_uint2(kb1[i * 2 + h], kb2[i * 2 + h]);
                }
        }
        __syncthreads();
    }
}

// ---------------------------------------------------------------------------
// exact fp32 rescue: per patch, rescore all near-min candidates
// ---------------------------------------------------------------------------
__global__ void rescue_kernel(const float* __restrict__ patches,
                              const float* __restrict__ vocab,
                              float* __restrict__ tokens) {
    const int p = blockIdx.x * 256 + threadIdx.x;
    if (p >= NPATCH) return;
    uint32_t m = 0xFFFFFFFFu;
#pragma unroll 8
    for (int s = 0; s < 64; s++) m = min(m, g_cand[s * NPATCH + p].x);
    const float thr = unkey(m) + 2.5f;

    float bestv = 3.4e38f;
    int   besti = 0x7FFFFFFF;
    const float* pp = patches + (size_t)p * D_DIM;
#pragma unroll 1
    for (int s = 0; s < 64; s++) {
        const uint2 c = g_cand[s * NPATCH + p];
#pragma unroll
        for (int e = 0; e < 2; e++) {
            const uint32_t k = e ? c.y : c.x;
            if (unkey(k) <= thr) {
                const int vi = (int)(k & 0xFFFu);
                const float* vp = vocab + (size_t)vi * D_DIM;
                float dot = 0.f;
#pragma unroll 8
                for (int k4 = 0; k4 < 64; k4++) {
                    const float4 a = *(const float4*)(pp + k4 * 4);
                    const float4 b = *(const float4*)(vp + k4 * 4);
                    dot += a.x * b.x; dot += a.y * b.y;
                    dot += a.z * b.z; dot += a.w * b.w;
                }
                const float se = __ldg(&g_v2[vi]) - 2.f * dot;
                if (se < bestv || (se == bestv && vi < besti)) { bestv = se; besti = vi; }
            }
        }
    }
    tokens[p] = (float)besti;
}

// ---------------------------------------------------------------------------
extern "C" void kernel_launch(void* const* d_in, const int* in_sizes, int n_in,
                              void* d_out, int out_size) {
    const float* images = (const float*)d_in[0];   // [64, 256, 256]
    const float* vocab  = (const float*)d_in[1];   // [4096, 256]
    float* out = (float*)d_out;

    const int npix = in_sizes[0];                  // 4194304
    const int nvoc = in_sizes[1];                  // 1048576
    const int V  = nvoc / D_DIM;                   // 4096

    float* patches = out;
    float* tokens  = out + npix;

    v2_kernel<<<(V + 7) / 8, 256>>>(vocab, V);
    vocab_bf_kernel<<<(nvoc + 255) / 256, 256>>>(vocab, nvoc);
    patchify_bf_kernel<<<(npix + 255) / 256, 256>>>(images, patches, npix);

    cudaFuncSetAttribute(vq_kernel, cudaFuncAttributeMaxDynamicSharedMemorySize, SMEM_BYTES);
    vq_kernel<<<NVT * NGRP, 256, SMEM_BYTES>>>();

    rescue_kernel<<<NPATCH / 256, 256>>>(patches, vocab, tokens);
}

// round 6
// speedup vs baseline: 2.3922x; 2.3922x over previous
#include <cuda_runtime.h>
#include <cuda_bf16.h>
#include <cstdint>

#define D_DIM   256
#define NPATCH  16384
#define VOCAB   4096

#define NVT     16          // vocab tiles of 256 rows
#define VTN     256         // vocab rows per tile
#define CHM     64          // patches per chunk
#define NGRP    9           // patch groups (grid = 144)
#define NCHUNK  (NPATCH / CHM)   // 256 chunks total

#define B_BYTES (VTN * 512)              // 131072 (vocab tile, full K, bf16)
#define A_STAGE (CHM * 512)              // 32768
#define SMEM_BYTES (B_BYTES + 2 * A_STAGE)  // 196608

__device__ float         g_v2[VOCAB];
__device__ __nv_bfloat16 g_pb[NPATCH * D_DIM];
__device__ __nv_bfloat16 g_vb[VOCAB * D_DIM];
__device__ uint2         g_cand[NPATCH * 64];   // [patch][vt*4+wn] best-2 keys

#define CP_ASYNC16(dst, src) \
    asm volatile("cp.async.cg.shared.global [%0], [%1], 16;" :: "r"((uint32_t)(dst)), "l"(src))
#define CP_COMMIT() asm volatile("cp.async.commit_group;" ::: "memory")

__device__ __forceinline__ void mma16(float* c, uint32_t a0, uint32_t a1, uint32_t a2, uint32_t a3,
                                      uint32_t b0, uint32_t b1) {
    asm("mma.sync.aligned.m16n8k16.row.col.f32.bf16.bf16.f32 "
        "{%0,%1,%2,%3}, {%4,%5,%6,%7}, {%8,%9}, {%0,%1,%2,%3};"
        : "+f"(c[0]), "+f"(c[1]), "+f"(c[2]), "+f"(c[3])
        : "r"(a0), "r"(a1), "r"(a2), "r"(a3), "r"(b0), "r"(b1));
}

// order-preserving float->uint key, vocab idx in low 12 bits
__device__ __forceinline__ uint32_t fkey(float s, int n) {
    uint32_t b = __float_as_uint(s);
    uint32_t u = b ^ (uint32_t)(((int32_t)b >> 31) | 0x80000000);
    return (u & 0xFFFFF000u) | (uint32_t)n;
}
__device__ __forceinline__ float unkey(uint32_t key) {
    uint32_t u = key & 0xFFFFF000u;
    uint32_t b = (u & 0x80000000u) ? (u ^ 0x80000000u) : ~u;
    return __uint_as_float(b);
}

// within a 32-k block: lane t's 16B covers both k16 groups (proven layout)
__device__ __forceinline__ int perm32(int k) {
    return ((k & 7) >> 1) * 8 + ((k >> 4) & 1) * 4 + ((k >> 3) & 1) * 2 + (k & 1);
}

// ---------------------------------------------------------------------------
// prep kernels
// ---------------------------------------------------------------------------
__global__ void v2_kernel(const float* __restrict__ vocab, int V) {
    int v = blockIdx.x * 8 + (threadIdx.x >> 5);
    int lane = threadIdx.x & 31;
    if (v >= V) return;
    const float* row = vocab + v * D_DIM;
    float s = 0.f;
#pragma unroll
    for (int k = lane; k < D_DIM; k += 32) { float x = row[k]; s += x * x; }
#pragma unroll
    for (int o = 16; o > 0; o >>= 1) s += __shfl_down_sync(0xffffffffu, s, o);
    if (lane == 0) g_v2[v] = s;
}

__global__ void patchify_bf_kernel(const float* __restrict__ images,
                                   float* __restrict__ patches, int total) {
    int idx = blockIdx.x * blockDim.x + threadIdx.x;
    if (idx >= total) return;
    int d = idx & 255, n = (idx >> 8) & 255, b = idx >> 16;
    int ph = n >> 4, pw = n & 15, i = d >> 4, j = d & 15;
    float x = images[(b << 16) + ((ph * 16 + i) << 8) + pw * 16 + j];
    patches[idx] = x;
    g_pb[(idx & ~255) + (d & ~31) + perm32(d & 31)] = __float2bfloat16_rn(x);
}

__global__ void vocab_bf_kernel(const float* __restrict__ vocab, int total) {
    int idx = blockIdx.x * blockDim.x + threadIdx.x;
    if (idx >= total) return;
    int d = idx & 255;
    g_vb[(idx & ~255) + (d & ~31) + perm32(d & 31)] = __float2bfloat16_rn(vocab[idx]);
}

// ---------------------------------------------------------------------------
// vq: vocab tile resident (full K), stream patch chunks, best2 per 64-col group
// ---------------------------------------------------------------------------
__global__ __launch_bounds__(256, 1)
void vq_kernel() {
    extern __shared__ char sm[];
    const uint32_t smem = (uint32_t)__cvta_generic_to_shared(sm);
    const uint32_t smB = smem;
    const uint32_t smA = smem + B_BYTES;

    const int tid  = threadIdx.x;
    const int lane = tid & 31;
    const int wid  = tid >> 5;
    const int g    = lane >> 2;
    const int t    = lane & 3;
    const int wm   = wid & 1;           // 2 m-warps (32 patch rows)
    const int wn   = wid >> 1;          // 4 n-warps (64 vocab cols)

    const int vt  = blockIdx.x & 15;
    const int grp = blockIdx.x >> 4;
    const int c0  = (grp * NCHUNK) / NGRP;
    const int c1  = ((grp + 1) * NCHUNK) / NGRP;

    // ---- prologue: resident B tile + A chunk c0, one commit group ----
    {
        const __nv_bfloat16* srcB = g_vb + (size_t)(vt * VTN + tid) * D_DIM;
        const uint32_t dB = smB + tid * 512;
        const uint32_t sw = (uint32_t)(tid & 7) << 2;
#pragma unroll
        for (int u = 0; u < 32; u++)
            CP_ASYNC16(dB + (((uint32_t)u ^ sw) << 4), srcB + u * 8);
        const int r = tid >> 2, q = tid & 3;
        const __nv_bfloat16* srcA = g_pb + (size_t)(c0 * CHM + r) * D_DIM;
        const uint32_t swA = (uint32_t)(r & 7) << 2;
#pragma unroll
        for (int uu = 0; uu < 8; uu++) {
            const int u = q * 8 + uu;
            CP_ASYNC16(smA + r * 512 + (((uint32_t)u ^ swA) << 4), srcA + u * 8);
        }
        CP_COMMIT();
    }

    // v2 for owned columns (16 per thread), in registers
    float v2r[16];
#pragma unroll
    for (int j = 0; j < 8; j++)
#pragma unroll
        for (int e = 0; e < 2; e++)
            v2r[j * 2 + e] = __ldg(g_v2 + vt * VTN + wn * 64 + j * 8 + 2 * t + e);

#define BEST2(sl, kv) do { \
        uint32_t _k = (kv); \
        uint32_t _x1 = max(kb1[sl], _k); \
        kb1[sl] = min(kb1[sl], _k); \
        kb2[sl] = min(kb2[sl], _x1); \
    } while (0)

#pragma unroll 1
    for (int c = c0; c < c1; c++) {
        const int lc = c - c0;
        // prefetch next A chunk into the other stage
        if (c + 1 < c1) {
            const int r = tid >> 2, q = tid & 3;
            const __nv_bfloat16* srcA = g_pb + (size_t)((c + 1) * CHM + r) * D_DIM;
            const uint32_t dA = smA + ((lc + 1) & 1) * A_STAGE + r * 512;
            const uint32_t swA = (uint32_t)(r & 7) << 2;
#pragma unroll
            for (int uu = 0; uu < 8; uu++) {
                const int u = q * 8 + uu;
                CP_ASYNC16(dA + (((uint32_t)u ^ swA) << 4), srcA + u * 8);
            }
            CP_COMMIT();
            asm volatile("cp.async.wait_group 1;" ::: "memory");
        } else {
            asm volatile("cp.async.wait_group 0;" ::: "memory");
        }
        __syncthreads();

        const char* Ab = sm + B_BYTES + (lc & 1) * A_STAGE;
        float acc[2][8][4];
#pragma unroll
        for (int i = 0; i < 2; i++)
#pragma unroll
            for (int j = 0; j < 8; j++)
#pragma unroll
                for (int e = 0; e < 4; e++) acc[i][j][e] = 0.f;

#pragma unroll
        for (int kb = 0; kb < 8; kb++) {
            const uint32_t aoff = (uint32_t)((((kb ^ g) << 2) | t) << 4);
            uint4 af[2][2];
#pragma unroll
            for (int i = 0; i < 2; i++)
#pragma unroll
                for (int h = 0; h < 2; h++)
                    af[i][h] = *(const uint4*)(Ab + (wm * 32 + i * 16 + h * 8 + g) * 512 + aoff);
#pragma unroll
            for (int j = 0; j < 8; j++) {
                const int n = wn * 64 + j * 8 + g;      // n & 7 == g
                const uint4 bf = *(const uint4*)(sm + n * 512 + aoff);
#pragma unroll
                for (int i = 0; i < 2; i++) {
                    float* cacc = acc[i][j];
                    mma16(cacc, af[i][0].x, af[i][1].x, af[i][0].y, af[i][1].y, bf.x, bf.y);
                    mma16(cacc, af[i][0].z, af[i][1].z, af[i][0].w, af[i][1].w, bf.z, bf.w);
                }
            }
        }

        // epilogue: per-row best2 over this warp's 64 cols
        uint32_t kb1[4], kb2[4];
#pragma unroll
        for (int sl = 0; sl < 4; sl++) { kb1[sl] = 0xFFFFFFFFu; kb2[sl] = 0xFFFFFFFFu; }
#pragma unroll
        for (int j = 0; j < 8; j++) {
            const int nn = vt * VTN + wn * 64 + j * 8 + 2 * t;
#pragma unroll
            for (int i = 0; i < 2; i++) {
                BEST2(i * 2 + 0, fkey(v2r[j * 2 + 0] - 2.f * acc[i][j][0], nn));
                BEST2(i * 2 + 0, fkey(v2r[j * 2 + 1] - 2.f * acc[i][j][1], nn + 1));
                BEST2(i * 2 + 1, fkey(v2r[j * 2 + 0] - 2.f * acc[i][j][2], nn));
                BEST2(i * 2 + 1, fkey(v2r[j * 2 + 1] - 2.f * acc[i][j][3], nn + 1));
            }
        }
        // combine across the 4 t-lanes sharing each row
#pragma unroll
        for (int o = 1; o <= 2; o <<= 1) {
#pragma unroll
            for (int sl = 0; sl < 4; sl++) {
                const uint32_t o1 = __shfl_xor_sync(0xffffffffu, kb1[sl], o);
                const uint32_t o2 = __shfl_xor_sync(0xffffffffu, kb2[sl], o);
                const uint32_t x1 = max(kb1[sl], o1);
                kb1[sl] = min(kb1[sl], o1);
                kb2[sl] = min(min(kb2[sl], o2), x1);
            }
        }
        if (t == 0) {
#pragma unroll
            for (int i = 0; i < 2; i++)
#pragma unroll
                for (int h = 0; h < 2; h++) {
                    const int row = c * CHM + wm * 32 + i * 16 + h * 8 + g;
                    g_cand[row * 64 + vt * 4 + wn] =
                        make_uint2(kb1[i * 2 + h], kb2[i * 2 + h]);
                }
        }
        __syncthreads();
    }
}

// ---------------------------------------------------------------------------
// exact fp32 rescue: one WARP per patch, coalesced candidates, cooperative dots
// ---------------------------------------------------------------------------
__global__ __launch_bounds__(256)
void rescue_kernel(const float* __restrict__ patches,
                   const float* __restrict__ vocab,
                   float* __restrict__ tokens) {
    const int p    = (blockIdx.x * 256 + threadIdx.x) >> 5;   // warp id == patch
    const int lane = threadIdx.x & 31;
    if (p >= NPATCH) return;

    // candidate keys for this patch: 64 contiguous uint2 -> 2 per lane
    const uint2 c0 = g_cand[p * 64 + lane];
    const uint2 c1 = g_cand[p * 64 + 32 + lane];
    uint32_t keys[4] = {c0.x, c0.y, c1.x, c1.y};

    // warp-min over best1 keys -> threshold
    uint32_t kmin = min(c0.x, c1.x);
#pragma unroll
    for (int o = 16; o > 0; o >>= 1)
        kmin = min(kmin, __shfl_xor_sync(0xffffffffu, kmin, o));
    const float thr = unkey(kmin) + 2.0f;

    // patch row in registers: 8 floats per lane
    const float* pp = patches + (size_t)p * D_DIM;
    const float4 pa = *(const float4*)(pp + lane * 8);
    const float4 pb = *(const float4*)(pp + lane * 8 + 4);

    float bestv = 3.4e38f;
    int   besti = 0x7FFFFFFF;
#pragma unroll
    for (int r = 0; r < 4; r++) {
        unsigned mask = __ballot_sync(0xffffffffu, unkey(keys[r]) <= thr);
        while (mask) {
            const int src = __ffs(mask) - 1;
            mask &= mask - 1;
            const int vi = (int)(__shfl_sync(0xffffffffu, keys[r], src) & 0xFFFu);
            const float* vp = vocab + (size_t)vi * D_DIM;
            const float4 va = *(const float4*)(vp + lane * 8);
            const float4 vb = *(const float4*)(vp + lane * 8 + 4);
            float d = pa.x * va.x + pa.y * va.y + pa.z * va.z + pa.w * va.w
                    + pb.x * vb.x + pb.y * vb.y + pb.z * vb.z + pb.w * vb.w;
#pragma unroll
            for (int o = 16; o > 0; o >>= 1)
                d += __shfl_xor_sync(0xffffffffu, d, o);
            const float se = __ldg(&g_v2[vi]) - 2.f * d;
            if (se < bestv || (se == bestv && vi < besti)) { bestv = se; besti = vi; }
        }
    }
    if (lane == 0) tokens[p] = (float)besti;
}

// ---------------------------------------------------------------------------
extern "C" void kernel_launch(void* const* d_in, const int* in_sizes, int n_in,
                              void* d_out, int out_size) {
    const float* images = (const float*)d_in[0];   // [64, 256, 256]
    const float* vocab  = (const float*)d_in[1];   // [4096, 256]
    float* out = (float*)d_out;

    const int npix = in_sizes[0];                  // 4194304
    const int nvoc = in_sizes[1];                  // 1048576
    const int V  = nvoc / D_DIM;                   // 4096

    float* patches = out;
    float* tokens  = out + npix;

    v2_kernel<<<(V + 7) / 8, 256>>>(vocab, V);
    vocab_bf_kernel<<<(nvoc + 255) / 256, 256>>>(vocab, nvoc);
    patchify_bf_kernel<<<(npix + 255) / 256, 256>>>(images, patches, npix);

    cudaFuncSetAttribute(vq_kernel, cudaFuncAttributeMaxDynamicSharedMemorySize, SMEM_BYTES);
    vq_kernel<<<NVT * NGRP, 256, SMEM_BYTES>>>();

    rescue_kernel<<<(NPATCH * 32) / 256, 256>>>(patches, vocab, tokens);
}

// round 7
// speedup vs baseline: 2.5853x; 1.0807x over previous
#include <cuda_runtime.h>
#include <cuda_bf16.h>
#include <cstdint>

#define D_DIM   256
#define NPATCH  16384
#define VOCAB   4096

#define NVT     16          // vocab tiles of 256 rows
#define VTN     256         // vocab rows per tile
#define CHM     64          // patches per chunk
#define NGRP    9           // patch groups (grid = 144)
#define NCHUNK  (NPATCH / CHM)   // 256 chunks total

#define B_BYTES (VTN * 512)              // 131072 (vocab tile, full K, bf16)
#define A_STAGE (CHM * 512)              // 32768
#define SMEM_BYTES (B_BYTES + 2 * A_STAGE)  // 196608

__device__ float         g_v2[VOCAB];
__device__ __nv_bfloat16 g_pb[NPATCH * D_DIM];
__device__ __nv_bfloat16 g_vb[VOCAB * D_DIM];
__device__ uint2         g_cand[NPATCH * 128];   // [patch][vt*8+wn] best-2 keys

#define CP_ASYNC16(dst, src) \
    asm volatile("cp.async.cg.shared.global [%0], [%1], 16;" :: "r"((uint32_t)(dst)), "l"(src))
#define CP_COMMIT() asm volatile("cp.async.commit_group;" ::: "memory")

__device__ __forceinline__ void mma16(float* c, uint32_t a0, uint32_t a1, uint32_t a2, uint32_t a3,
                                      uint32_t b0, uint32_t b1) {
    asm("mma.sync.aligned.m16n8k16.row.col.f32.bf16.bf16.f32 "
        "{%0,%1,%2,%3}, {%4,%5,%6,%7}, {%8,%9}, {%0,%1,%2,%3};"
        : "+f"(c[0]), "+f"(c[1]), "+f"(c[2]), "+f"(c[3])
        : "r"(a0), "r"(a1), "r"(a2), "r"(a3), "r"(b0), "r"(b1));
}

// order-preserving float->uint key, vocab idx in low 12 bits
__device__ __forceinline__ uint32_t fkey(float s, int n) {
    uint32_t b = __float_as_uint(s);
    uint32_t u = b ^ (uint32_t)(((int32_t)b >> 31) | 0x80000000);
    return (u & 0xFFFFF000u) | (uint32_t)n;
}
__device__ __forceinline__ float unkey(uint32_t key) {
    uint32_t u = key & 0xFFFFF000u;
    uint32_t b = (u & 0x80000000u) ? (u ^ 0x80000000u) : ~u;
    return __uint_as_float(b);
}

// within a 32-k block: lane t's 16B covers both k16 groups (proven layout)
__device__ __forceinline__ int perm32(int k) {
    return ((k & 7) >> 1) * 8 + ((k >> 4) & 1) * 4 + ((k >> 3) & 1) * 2 + (k & 1);
}

// ---------------------------------------------------------------------------
// prep kernels
// ---------------------------------------------------------------------------
__global__ void v2_kernel(const float* __restrict__ vocab, int V) {
    int v = blockIdx.x * 8 + (threadIdx.x >> 5);
    int lane = threadIdx.x & 31;
    if (v >= V) return;
    const float* row = vocab + v * D_DIM;
    float s = 0.f;
#pragma unroll
    for (int k = lane; k < D_DIM; k += 32) { float x = row[k]; s += x * x; }
#pragma unroll
    for (int o = 16; o > 0; o >>= 1) s += __shfl_down_sync(0xffffffffu, s, o);
    if (lane == 0) g_v2[v] = s;
}

__global__ void patchify_bf_kernel(const float* __restrict__ images,
                                   float* __restrict__ patches, int total) {
    int idx = blockIdx.x * blockDim.x + threadIdx.x;
    if (idx >= total) return;
    int d = idx & 255, n = (idx >> 8) & 255, b = idx >> 16;
    int ph = n >> 4, pw = n & 15, i = d >> 4, j = d & 15;
    float x = images[(b << 16) + ((ph * 16 + i) << 8) + pw * 16 + j];
    patches[idx] = x;
    g_pb[(idx & ~255) + (d & ~31) + perm32(d & 31)] = __float2bfloat16_rn(x);
}

__global__ void vocab_bf_kernel(const float* __restrict__ vocab, int total) {
    int idx = blockIdx.x * blockDim.x + threadIdx.x;
    if (idx >= total) return;
    int d = idx & 255;
    g_vb[(idx & ~255) + (d & ~31) + perm32(d & 31)] = __float2bfloat16_rn(vocab[idx]);
}

// ---------------------------------------------------------------------------
// vq: vocab tile resident (full K), stream patch chunks, 16 warps, warp tile 32x32
// ---------------------------------------------------------------------------
__global__ __launch_bounds__(512, 1)
void vq_kernel() {
    extern __shared__ char sm[];
    const uint32_t smem = (uint32_t)__cvta_generic_to_shared(sm);
    const uint32_t smB = smem;
    const uint32_t smA = smem + B_BYTES;

    const int tid  = threadIdx.x;
    const int lane = tid & 31;
    const int wid  = tid >> 5;
    const int g    = lane >> 2;
    const int t    = lane & 3;
    const int wm   = wid & 1;           // 2 m-warps (32 patch rows)
    const int wn   = wid >> 1;          // 8 n-warps (32 vocab cols)

    const int vt  = blockIdx.x & 15;
    const int grp = blockIdx.x >> 4;
    const int c0  = (grp * NCHUNK) / NGRP;
    const int c1  = ((grp + 1) * NCHUNK) / NGRP;

    // ---- prologue: resident B tile + A chunk c0, one commit group ----
    {
        const int rB = tid >> 1, hB = tid & 1;          // 256 rows x 2 halves
        const __nv_bfloat16* srcB = g_vb + (size_t)(vt * VTN + rB) * D_DIM + hB * 128;
        const uint32_t dB = smB + rB * 512;
        const uint32_t swB = (uint32_t)(rB & 7) << 2;
#pragma unroll
        for (int uu = 0; uu < 16; uu++) {
            const int u = hB * 16 + uu;
            CP_ASYNC16(dB + (((uint32_t)u ^ swB) << 4), srcB + uu * 8);
        }
        const int rA = tid >> 3, qA = tid & 7;          // 64 rows x 8 quads
        const __nv_bfloat16* srcA = g_pb + (size_t)(c0 * CHM + rA) * D_DIM + qA * 32;
        const uint32_t swA = (uint32_t)(rA & 7) << 2;
#pragma unroll
        for (int uu = 0; uu < 4; uu++) {
            const int u = qA * 4 + uu;
            CP_ASYNC16(smA + rA * 512 + (((uint32_t)u ^ swA) << 4), srcA + uu * 8);
        }
        CP_COMMIT();
    }

    // v2 for owned columns (8 per thread), in registers
    float v2r[8];
#pragma unroll
    for (int j = 0; j < 4; j++)
#pragma unroll
        for (int e = 0; e < 2; e++)
            v2r[j * 2 + e] = __ldg(g_v2 + vt * VTN + wn * 32 + j * 8 + 2 * t + e);

#define BEST2(sl, kv) do { \
        uint32_t _k = (kv); \
        uint32_t _x1 = max(kb1[sl], _k); \
        kb1[sl] = min(kb1[sl], _k); \
        kb2[sl] = min(kb2[sl], _x1); \
    } while (0)

#pragma unroll 1
    for (int c = c0; c < c1; c++) {
        const int lc = c - c0;
        // prefetch next A chunk into the other stage
        if (c + 1 < c1) {
            const int rA = tid >> 3, qA = tid & 7;
            const __nv_bfloat16* srcA = g_pb + (size_t)((c + 1) * CHM + rA) * D_DIM + qA * 32;
            const uint32_t dA = smA + ((lc + 1) & 1) * A_STAGE + rA * 512;
            const uint32_t swA = (uint32_t)(rA & 7) << 2;
#pragma unroll
            for (int uu = 0; uu < 4; uu++) {
                const int u = qA * 4 + uu;
                CP_ASYNC16(dA + (((uint32_t)u ^ swA) << 4), srcA + uu * 8);
            }
            CP_COMMIT();
            asm volatile("cp.async.wait_group 1;" ::: "memory");
        } else {
            asm volatile("cp.async.wait_group 0;" ::: "memory");
        }
        __syncthreads();

        const char* Ab = sm + B_BYTES + (lc & 1) * A_STAGE;
        float acc[2][4][4];
#pragma unroll
        for (int i = 0; i < 2; i++)
#pragma unroll
            for (int j = 0; j < 4; j++)
#pragma unroll
                for (int e = 0; e < 4; e++) acc[i][j][e] = 0.f;

#pragma unroll
        for (int kb = 0; kb < 8; kb++) {
            const uint32_t aoff = (uint32_t)((((kb ^ g) << 2) | t) << 4);
            uint4 af[2][2];
#pragma unroll
            for (int i = 0; i < 2; i++)
#pragma unroll
                for (int h = 0; h < 2; h++)
                    af[i][h] = *(const uint4*)(Ab + (wm * 32 + i * 16 + h * 8 + g) * 512 + aoff);
#pragma unroll
            for (int j = 0; j < 4; j++) {
                const int n = wn * 32 + j * 8 + g;      // n & 7 == g
                const uint4 bf = *(const uint4*)(sm + n * 512 + aoff);
#pragma unroll
                for (int i = 0; i < 2; i++) {
                    float* cacc = acc[i][j];
                    mma16(cacc, af[i][0].x, af[i][1].x, af[i][0].y, af[i][1].y, bf.x, bf.y);
                    mma16(cacc, af[i][0].z, af[i][1].z, af[i][0].w, af[i][1].w, bf.z, bf.w);
                }
            }
        }

        // epilogue: per-row best2 over this warp's 32 cols
        uint32_t kb1[4], kb2[4];
#pragma unroll
        for (int sl = 0; sl < 4; sl++) { kb1[sl] = 0xFFFFFFFFu; kb2[sl] = 0xFFFFFFFFu; }
#pragma unroll
        for (int j = 0; j < 4; j++) {
            const int nn = vt * VTN + wn * 32 + j * 8 + 2 * t;
#pragma unroll
            for (int i = 0; i < 2; i++) {
                BEST2(i * 2 + 0, fkey(v2r[j * 2 + 0] - 2.f * acc[i][j][0], nn));
                BEST2(i * 2 + 0, fkey(v2r[j * 2 + 1] - 2.f * acc[i][j][1], nn + 1));
                BEST2(i * 2 + 1, fkey(v2r[j * 2 + 0] - 2.f * acc[i][j][2], nn));
                BEST2(i * 2 + 1, fkey(v2r[j * 2 + 1] - 2.f * acc[i][j][3], nn + 1));
            }
        }
        // combine across the 4 t-lanes sharing each row
#pragma unroll
        for (int o = 1; o <= 2; o <<= 1) {
#pragma unroll
            for (int sl = 0; sl < 4; sl++) {
                const uint32_t o1 = __shfl_xor_sync(0xffffffffu, kb1[sl], o);
                const uint32_t o2 = __shfl_xor_sync(0xffffffffu, kb2[sl], o);
                const uint32_t x1 = max(kb1[sl], o1);
                kb1[sl] = min(kb1[sl], o1);
                kb2[sl] = min(min(kb2[sl], o2), x1);
            }
        }
        if (t == 0) {
#pragma unroll
            for (int i = 0; i < 2; i++)
#pragma unroll
                for (int h = 0; h < 2; h++) {
                    const int row = c * CHM + wm * 32 + i * 16 + h * 8 + g;
                    g_cand[row * 128 + vt * 8 + wn] =
                        make_uint2(kb1[i * 2 + h], kb2[i * 2 + h]);
                }
        }
        __syncthreads();
    }
}

// ---------------------------------------------------------------------------
// exact fp32 rescue: one WARP per patch, coalesced candidates, cooperative dots
// ---------------------------------------------------------------------------
__global__ __launch_bounds__(256)
void rescue_kernel(const float* __restrict__ patches,
                   const float* __restrict__ vocab,
                   float* __restrict__ tokens) {
    const int p    = (blockIdx.x * 256 + threadIdx.x) >> 5;   // warp id == patch
    const int lane = threadIdx.x & 31;
    if (p >= NPATCH) return;

    // candidate keys for this patch: 128 contiguous uint2 -> 4 per lane
    uint2 cc[4];
#pragma unroll
    for (int r = 0; r < 4; r++) cc[r] = g_cand[p * 128 + r * 32 + lane];
    uint32_t keys[8];
#pragma unroll
    for (int r = 0; r < 4; r++) { keys[r * 2] = cc[r].x; keys[r * 2 + 1] = cc[r].y; }

    // warp-min over best1 keys -> threshold
    uint32_t kmin = min(min(cc[0].x, cc[1].x), min(cc[2].x, cc[3].x));
#pragma unroll
    for (int o = 16; o > 0; o >>= 1)
        kmin = min(kmin, __shfl_xor_sync(0xffffffffu, kmin, o));
    const float thr = unkey(kmin) + 2.0f;

    // patch row in registers: 8 floats per lane
    const float* pp = patches + (size_t)p * D_DIM;
    const float4 pa = *(const float4*)(pp + lane * 8);
    const float4 pb = *(const float4*)(pp + lane * 8 + 4);

    float bestv = 3.4e38f;
    int   besti = 0x7FFFFFFF;
#pragma unroll
    for (int r = 0; r < 8; r++) {
        unsigned mask = __ballot_sync(0xffffffffu, unkey(keys[r]) <= thr);
        while (mask) {
            const int src = __ffs(mask) - 1;
            mask &= mask - 1;
            const int vi = (int)(__shfl_sync(0xffffffffu, keys[r], src) & 0xFFFu);
            const float* vp = vocab + (size_t)vi * D_DIM;
            const float4 va = *(const float4*)(vp + lane * 8);
            const float4 vb = *(const float4*)(vp + lane * 8 + 4);
            float d = pa.x * va.x + pa.y * va.y + pa.z * va.z + pa.w * va.w
                    + pb.x * vb.x + pb.y * vb.y + pb.z * vb.z + pb.w * vb.w;
#pragma unroll
            for (int o = 16; o > 0; o >>= 1)
                d += __shfl_xor_sync(0xffffffffu, d, o);
            const float se = __ldg(&g_v2[vi]) - 2.f * d;
            if (se < bestv || (se == bestv && vi < besti)) { bestv = se; besti = vi; }
        }
    }
    if (lane == 0) tokens[p] = (float)besti;
}

// ---------------------------------------------------------------------------
extern "C" void kernel_launch(void* const* d_in, const int* in_sizes, int n_in,
                              void* d_out, int out_size) {
    const float* images = (const float*)d_in[0];   // [64, 256, 256]
    const float* vocab  = (const float*)d_in[1];   // [4096, 256]
    float* out = (float*)d_out;

    const int npix = in_sizes[0];                  // 4194304
    const int nvoc = in_sizes[1];                  // 1048576
    const int V  = nvoc / D_DIM;                   // 4096

    float* patches = out;
    float* tokens  = out + npix;

    v2_kernel<<<(V + 7) / 8, 256>>>(vocab, V);
    vocab_bf_kernel<<<(nvoc + 255) / 256, 256>>>(vocab, nvoc);
    patchify_bf_kernel<<<(npix + 255) / 256, 256>>>(images, patches, npix);

    cudaFuncSetAttribute(vq_kernel, cudaFuncAttributeMaxDynamicSharedMemorySize, SMEM_BYTES);
    vq_kernel<<<NVT * NGRP, 512, SMEM_BYTES>>>();

    rescue_kernel<<<(NPATCH * 32) / 256, 256>>>(patches, vocab, tokens);
}